// round 14
// baseline (speedup 1.0000x reference)
#include <cuda_runtime.h>
#include <cuda_fp16.h>
#include <cstdint>

// ---------------------------------------------------------------------------
// Problem constants
// ---------------------------------------------------------------------------
#define NB    128
#define NQ    36
#define NN    36
#define IND   1024
#define NKER  8
#define OUTK  128
#define OUTD  1024
#define BQ    (NB * NQ)          // 4608
#define MT    36                 // M row-tiles of 128
#define CHUNKS 32                // K chunks of 32 over IND=1024
#define TILE_B 8192              // one A/B tile: 128 rows x 32 fp16 x 2B

#define NPREP 256                // prep tasks
#define NTASK (NPREP + BQ)       // 4864
#define NPERS 592                // persistent agg blocks = 148 SM x 4 (one wave)

typedef unsigned long long ull;

// ---------------------------------------------------------------------------
// Device-global scratch. A (agg) and B (conv_w^T) single fp16 (validated:
// output rel err 2.94e-4 vs 1e-3 threshold).
// Tile: 128 rows x 32 cols fp16, rows of 64B, 16B groups XOR-swizzled by
// ((row>>1)&3) -> conflict-free ldmatrix. Each tile is 8KB contiguous.
// A: [kker][mt128(36)][chunk(32)] x tile;  B: [kker][chunk(32)] x tile.
// ---------------------------------------------------------------------------
__device__ __align__(128) __half g_a_hi[(size_t)NKER * MT * CHUNKS * (TILE_B / 2)];
__device__ __align__(128) __half g_b_hi[(size_t)NKER * CHUNKS * (TILE_B / 2)];

// ---------------------------------------------------------------------------
// PTX helpers (non-"a" features only: valid on plain sm_103 target)
// ---------------------------------------------------------------------------
__device__ __forceinline__ void fma2(ull& d, ull a, ull b) {
    asm("fma.rn.f32x2 %0, %1, %2, %0;" : "+l"(d) : "l"(a), "l"(b));
}
__device__ __forceinline__ ull pack2(float x) {
    ull r;
    asm("mov.b64 %0, {%1, %1};" : "=l"(r) : "r"(__float_as_uint(x)));
    return r;
}
__device__ __forceinline__ uint32_t smem_u32(const void* p) {
    uint32_t a;
    asm("{ .reg .u64 t; cvta.to.shared.u64 t, %1; cvt.u32.u64 %0, t; }" : "=r"(a) : "l"(p));
    return a;
}
__device__ __forceinline__ void ldx4(uint32_t* r, uint32_t addr) {
    asm volatile("ldmatrix.sync.aligned.m8n8.x4.shared.b16 {%0,%1,%2,%3}, [%4];"
                 : "=r"(r[0]), "=r"(r[1]), "=r"(r[2]), "=r"(r[3]) : "r"(addr));
}
__device__ __forceinline__ void mma16816(float* d, const uint32_t* a, const uint32_t* b) {
    asm volatile(
        "mma.sync.aligned.m16n8k16.row.col.f32.f16.f16.f32 "
        "{%0,%1,%2,%3}, {%4,%5,%6,%7}, {%8,%9}, {%0,%1,%2,%3};"
        : "+f"(d[0]), "+f"(d[1]), "+f"(d[2]), "+f"(d[3])
        : "r"(a[0]), "r"(a[1]), "r"(a[2]), "r"(a[3]), "r"(b[0]), "r"(b[1]));
}
__device__ __forceinline__ void mbar_init(uint32_t addr, uint32_t cnt) {
    asm volatile("mbarrier.init.shared.b64 [%0], %1;" :: "r"(addr), "r"(cnt) : "memory");
}
__device__ __forceinline__ void mbar_expect_tx(uint32_t addr, uint32_t bytes) {
    asm volatile("mbarrier.arrive.expect_tx.shared.b64 _, [%0], %1;"
                 :: "r"(addr), "r"(bytes) : "memory");
}
__device__ __forceinline__ void mbar_wait_acq(uint32_t addr, uint32_t parity) {
    asm volatile(
        "{\n\t.reg .pred P;\n\t"
        "W%=:\n\t"
        "mbarrier.try_wait.parity.acquire.cta.shared::cta.b64 P, [%0], %1;\n\t"
        "@!P bra W%=;\n\t}"
        :: "r"(addr), "r"(parity) : "memory");
}
__device__ __forceinline__ void bulk_g2s(uint32_t dst, const void* src, uint32_t bytes,
                                         uint32_t mbar) {
    asm volatile(
        "cp.async.bulk.shared::cta.global.mbarrier::complete_tx::bytes [%0], [%1], %2, [%3];"
        :: "r"(dst), "l"(src), "r"(bytes), "r"(mbar) : "memory");
}

// ---------------------------------------------------------------------------
// Kernel 1: persistent fused [prep | agg]. Grid = 592 = one full wave at
// 4 blocks/SM. Each block loops over tasks t = bid, bid+592, ... (8-9 tasks):
//   t <  256 : prep (conv_w -> B tile)
//   t >= 256 : agg for bq = t-256
// Eliminates 7+ wave transitions and the ragged 0.2-wave tail of the
// non-persistent 4864-block launch.
// ---------------------------------------------------------------------------
__global__ void __launch_bounds__(256, 4) k_agg(
    const float* __restrict__ feats, const float* __restrict__ coords,
    const float* __restrict__ mrho,  const float* __restrict__ mtheta,
    const float* __restrict__ prho,  const float* __restrict__ ptheta,
    const float* __restrict__ convw)
{
    __shared__ __align__(16) char smem_buf[16384];
    const int tid = threadIdx.x;

    for (int task = blockIdx.x; task < NTASK; task += NPERS) {

        if (task < NPREP) {
            // ---------------- prep role ----------------
            const int kc = task & 31;
            const int kk = task >> 5;

            float* s = reinterpret_cast<float*>(smem_buf);     // 32 x 128 floats
            const float4* src = reinterpret_cast<const float4*>(
                convw + (size_t)kk * (IND * OUTK) + (size_t)kc * (32 * OUTK));
            float4* sd = reinterpret_cast<float4*>(s);
#pragma unroll
            for (int i = 0; i < 4; i++)
                sd[tid + i * 256] = __ldg(&src[tid + i * 256]);
            __syncthreads();

            const size_t tbase = ((size_t)kk * CHUNKS + kc) * TILE_B;
            const int n   = tid & 127;
            const int gg  = (tid >> 7) * 2;
            const int swz = (n >> 1) & 3;
#pragma unroll
            for (int gi = 0; gi < 2; gi++) {
                const int g = gg + gi;
                union { __half h[8]; uint4 u; } H;
#pragma unroll
                for (int j = 0; j < 8; j++)
                    H.h[j] = __float2half_rn(s[(g * 8 + j) * 128 + n]);
                const uint32_t sw = (uint32_t)(n * 64 + 16 * (g ^ swz));
                *reinterpret_cast<uint4*>((char*)g_b_hi + tbase + sw) = H.u;
            }
            __syncthreads();   // smem_buf reused next task
            continue;
        }

        // ---------------- agg role ----------------
        const int bq = task - NPREP;
        ull* w2s = reinterpret_cast<ull*>(smem_buf);   // [NN][NKER], rows 64B

        if (tid < NN) {
            const float rho = coords[((size_t)bq * NN + tid) * 2 + 0];
            const float th  = coords[((size_t)bq * NN + tid) * 2 + 1];
            float w[NKER];
            float s = 0.0f;
            const float TWO_PI = 6.283185307179586f;
#pragma unroll
            for (int k = 0; k < NKER; k++) {
                const float dr = rho - __ldg(&mrho[k]);
                const float pr = __ldg(&prho[k]);
                const float wr = expf(-0.5f * dr * dr / (1e-14f + pr * pr));
                const float fa = fabsf(th - __ldg(&mtheta[k]));
                const float sa = fabsf(TWO_PI - fa);
                const float an = fminf(fa, sa);
                const float pt = __ldg(&ptheta[k]);
                const float wt = expf(-0.5f * an * an / (1e-14f + pt * pt));
                float wv = wr * wt;
                wv = isnan(wv) ? 0.0f : wv;
                w[k] = wv;
                s += wv;
            }
#pragma unroll
            for (int k = 0; k < NKER; k++)
                w2s[tid * NKER + k] = pack2(w[k] / s);
        }
        __syncthreads();

        ull acc[NKER][2];
#pragma unroll
        for (int k = 0; k < NKER; k++) { acc[k][0] = 0ULL; acc[k][1] = 0ULL; }

        const ulonglong2* p = reinterpret_cast<const ulonglong2*>(feats)
                            + (size_t)bq * (NN * IND / 4) + tid;
        const ulonglong2* wrow = reinterpret_cast<const ulonglong2*>(w2s);

#pragma unroll 6
        for (int n = 0; n < NN; n++) {
            const ulonglong2 f = __ldcs(p);     // streaming, evict-first
            p += IND / 4;
#pragma unroll
            for (int kp = 0; kp < 4; kp++) {
                const ulonglong2 wk = wrow[n * 4 + kp];
                fma2(acc[2 * kp + 0][0], f.x, wk.x);
                fma2(acc[2 * kp + 0][1], f.y, wk.x);
                fma2(acc[2 * kp + 1][0], f.x, wk.y);
                fma2(acc[2 * kp + 1][1], f.y, wk.y);
            }
        }

        const int row   = bq & 127;
        const int mt128 = bq >> 7;
        const int kc    = tid >> 3;
        const int g     = (tid >> 1) & 3;
        const int half_ = tid & 1;
        const uint32_t sw = (uint32_t)(row * 64 + 16 * (g ^ ((row >> 1) & 3)) + 8 * half_);

#pragma unroll
        for (int k = 0; k < NKER; k++) {
            float x0 = __uint_as_float((uint32_t)acc[k][0]);
            float x1 = __uint_as_float((uint32_t)(acc[k][0] >> 32));
            float x2 = __uint_as_float((uint32_t)acc[k][1]);
            float x3 = __uint_as_float((uint32_t)(acc[k][1] >> 32));

            union { __half h[4]; ull u; } H;
            H.h[0] = __float2half_rn(x0);
            H.h[1] = __float2half_rn(x1);
            H.h[2] = __float2half_rn(x2);
            H.h[3] = __float2half_rn(x3);

            const size_t tile = ((size_t)(k * MT + mt128) * CHUNKS + kc) * TILE_B;
            __stcs(reinterpret_cast<ull*>((char*)g_a_hi + tile + sw), H.u);
        }
        __syncthreads();   // w2s reused next task
    }
}

// ---------------------------------------------------------------------------
// Kernel 2: HMMA GEMM (= R13, best measured). Block 128x128, 8 warps (warp
// tile 64x32), 3 stages x 32KB (two K-chunks per stage), 96KB smem ->
// 2 blocks/SM, grid (36,8) = one wave.
// ---------------------------------------------------------------------------
#define NST 3
#define STG_B 32768   // A0 8K | B0 8K | A1 8K | B1 8K
#define DSM_B (NST * STG_B)   // 98304

__global__ void __launch_bounds__(256, 2) k_mma(float* __restrict__ out)
{
    extern __shared__ char dsm[];
    __shared__ __align__(8) ull s_mbar[NST];

    const uint32_t sbase = smem_u32(dsm);
    const uint32_t mb    = smem_u32(s_mbar);

    const int tid  = threadIdx.x;
    const int wid  = tid >> 5;
    const int lane = tid & 31;
    const int mt   = blockIdx.x;   // 0..35
    const int kk   = blockIdx.y;   // 0..7

    const int wm = (wid >> 2) * 64;   // warp M offset (0/64)
    const int wn = (wid & 3) * 32;    // warp N offset (0/32/64/96)

    const char* Ab = (const char*)g_a_hi + (size_t)(kk * MT + mt) * CHUNKS * TILE_B;
    const char* Bb = (const char*)g_b_hi + (size_t)kk * CHUNKS * TILE_B;

    auto issue_stage = [&](int it, int s) {
        const uint32_t sb = sbase + (uint32_t)s * STG_B;
        const uint32_t fb = mb + 8u * (uint32_t)s;
        const int c0 = 2 * it;
        mbar_expect_tx(fb, STG_B);
        bulk_g2s(sb + 0,     Ab + (size_t)c0 * TILE_B,       TILE_B, fb);
        bulk_g2s(sb + 8192,  Bb + (size_t)c0 * TILE_B,       TILE_B, fb);
        bulk_g2s(sb + 16384, Ab + (size_t)(c0 + 1) * TILE_B, TILE_B, fb);
        bulk_g2s(sb + 24576, Bb + (size_t)(c0 + 1) * TILE_B, TILE_B, fb);
    };

    if (tid == 0) {
#pragma unroll
        for (int s = 0; s < NST; s++) mbar_init(mb + 8u * s, 1);
    }
    __syncthreads();
    if (tid == 0) {
        issue_stage(0, 0);
        issue_stage(1, 1);
    }

    const int j  = lane >> 3;
    const int rr = lane & 7;
    const int a_row  = wm + ((j & 1) << 3) + rr;   // + 16*i
    const int a_gsel = j >> 1;                     // + 2*ss
    const int swzA   = (a_row >> 1) & 3;
    const int b_n    = wn + ((j >> 1) << 3) + rr;  // + 16*p
    const int b_gsel = j & 1;                      // + 2*ss
    const int swzB   = (b_n >> 1) & 3;

    float acc[4][4][4];
#pragma unroll
    for (int i = 0; i < 4; i++)
#pragma unroll
        for (int t = 0; t < 4; t++)
#pragma unroll
            for (int q = 0; q < 4; q++) acc[i][t][q] = 0.0f;

    int ph[NST] = {0, 0, 0};

    const int NIT = CHUNKS / 2;   // 16
    for (int it = 0; it < NIT; it++) {
        const int s = it % NST;
        mbar_wait_acq(mb + 8u * s, ph[s]);
        ph[s] ^= 1;

        const uint32_t sb = sbase + (uint32_t)s * STG_B;

#pragma unroll
        for (int co = 0; co < 2; co++) {
            const uint32_t ahb = sb + (uint32_t)co * 16384;
            const uint32_t bhb = ahb + 8192;

#pragma unroll
            for (int ss = 0; ss < 2; ss++) {
                uint32_t bh[8];
#pragma unroll
                for (int p = 0; p < 2; p++) {
                    const uint32_t boff = (uint32_t)((b_n + 16 * p) * 64
                                        + 16 * ((2 * ss + b_gsel) ^ swzB));
                    ldx4(&bh[4 * p], bhb + boff);
                }
#pragma unroll
                for (int i = 0; i < 4; i++) {
                    uint32_t ah[4];
                    const uint32_t aoff = (uint32_t)((a_row + 16 * i) * 64
                                        + 16 * ((2 * ss + a_gsel) ^ swzA));
                    ldx4(ah, ahb + aoff);
#pragma unroll
                    for (int t = 0; t < 4; t++)
                        mma16816(acc[i][t], ah, &bh[2 * t]);
                }
            }
        }

        __syncthreads();
        if (it + 2 < NIT && tid == 0)
            issue_stage(it + 2, (it + 2) % NST);
    }

    // epilogue
#pragma unroll
    for (int i = 0; i < 4; i++) {
        const int r0 = mt * 128 + wm + 16 * i + (lane >> 2);
#pragma unroll
        for (int t = 0; t < 4; t++) {
            const int cN = kk * OUTK + wn + 8 * t + 2 * (lane & 3);
            float2 v0; v0.x = acc[i][t][0]; v0.y = acc[i][t][1];
            float2 v1; v1.x = acc[i][t][2]; v1.y = acc[i][t][3];
            *reinterpret_cast<float2*>(out + (size_t)r0 * OUTD + cN)       = v0;
            *reinterpret_cast<float2*>(out + (size_t)(r0 + 8) * OUTD + cN) = v1;
        }
    }
}

// ---------------------------------------------------------------------------
extern "C" void kernel_launch(void* const* d_in, const int* in_sizes, int n_in,
                              void* d_out, int out_size)
{
    const float* feats  = (const float*)d_in[0];
    const float* coords = (const float*)d_in[1];
    const float* mrho   = (const float*)d_in[2];
    const float* mtheta = (const float*)d_in[3];
    const float* prho   = (const float*)d_in[4];
    const float* ptheta = (const float*)d_in[5];
    const float* convw  = (const float*)d_in[6];
    float* out = (float*)d_out;

    cudaFuncSetAttribute(k_mma, cudaFuncAttributeMaxDynamicSharedMemorySize, DSM_B);

    k_agg<<<NPERS, 256>>>(feats, coords, mrho, mtheta, prho, ptheta, convw);
    dim3 gg(MT, NKER);
    k_mma<<<gg, 256, DSM_B>>>(out);
}

// round 15
// speedup vs baseline: 1.0945x; 1.0945x over previous
#include <cuda_runtime.h>
#include <cuda_fp16.h>
#include <cstdint>

// ---------------------------------------------------------------------------
// Problem constants
// ---------------------------------------------------------------------------
#define NB    128
#define NQ    36
#define NN    36
#define IND   1024
#define NKER  8
#define OUTK  128
#define OUTD  1024
#define BQ    (NB * NQ)          // 4608
#define MT    36                 // M row-tiles of 128
#define CHUNKS 32                // K chunks of 32 over IND=1024
#define TILE_B 8192              // one A/B tile: 128 rows x 32 fp16 x 2B

#define NPREP 256                // prep blocks fused into agg launch

typedef unsigned long long ull;

// ---------------------------------------------------------------------------
// Device-global scratch. A (agg) and B (conv_w^T) single fp16 (validated:
// output rel err 2.94e-4 vs 1e-3 threshold).
// Tile: 128 rows x 32 cols fp16, rows of 64B, 16B groups XOR-swizzled by
// ((row>>1)&3) -> conflict-free ldmatrix. Each tile is 8KB contiguous.
// A: [kker][mt128(36)][chunk(32)] x tile;  B: [kker][chunk(32)] x tile.
// ---------------------------------------------------------------------------
__device__ __align__(128) __half g_a_hi[(size_t)NKER * MT * CHUNKS * (TILE_B / 2)];
__device__ __align__(128) __half g_b_hi[(size_t)NKER * CHUNKS * (TILE_B / 2)];

// ---------------------------------------------------------------------------
// PTX helpers (non-"a" features only: valid on plain sm_103 target)
// ---------------------------------------------------------------------------
__device__ __forceinline__ void fma2(ull& d, ull a, ull b) {
    asm("fma.rn.f32x2 %0, %1, %2, %0;" : "+l"(d) : "l"(a), "l"(b));
}
__device__ __forceinline__ ull pack2(float x) {
    ull r;
    asm("mov.b64 %0, {%1, %1};" : "=l"(r) : "r"(__float_as_uint(x)));
    return r;
}
__device__ __forceinline__ uint32_t smem_u32(const void* p) {
    uint32_t a;
    asm("{ .reg .u64 t; cvta.to.shared.u64 t, %1; cvt.u32.u64 %0, t; }" : "=r"(a) : "l"(p));
    return a;
}
__device__ __forceinline__ void ldx4(uint32_t* r, uint32_t addr) {
    asm volatile("ldmatrix.sync.aligned.m8n8.x4.shared.b16 {%0,%1,%2,%3}, [%4];"
                 : "=r"(r[0]), "=r"(r[1]), "=r"(r[2]), "=r"(r[3]) : "r"(addr));
}
__device__ __forceinline__ void mma16816(float* d, const uint32_t* a, const uint32_t* b) {
    asm volatile(
        "mma.sync.aligned.m16n8k16.row.col.f32.f16.f16.f32 "
        "{%0,%1,%2,%3}, {%4,%5,%6,%7}, {%8,%9}, {%0,%1,%2,%3};"
        : "+f"(d[0]), "+f"(d[1]), "+f"(d[2]), "+f"(d[3])
        : "r"(a[0]), "r"(a[1]), "r"(a[2]), "r"(a[3]), "r"(b[0]), "r"(b[1]));
}
__device__ __forceinline__ void mbar_init(uint32_t addr, uint32_t cnt) {
    asm volatile("mbarrier.init.shared.b64 [%0], %1;" :: "r"(addr), "r"(cnt) : "memory");
}
__device__ __forceinline__ void mbar_expect_tx(uint32_t addr, uint32_t bytes) {
    asm volatile("mbarrier.arrive.expect_tx.shared.b64 _, [%0], %1;"
                 :: "r"(addr), "r"(bytes) : "memory");
}
__device__ __forceinline__ void mbar_wait_acq(uint32_t addr, uint32_t parity) {
    asm volatile(
        "{\n\t.reg .pred P;\n\t"
        "W%=:\n\t"
        "mbarrier.try_wait.parity.acquire.cta.shared::cta.b64 P, [%0], %1;\n\t"
        "@!P bra W%=;\n\t}"
        :: "r"(addr), "r"(parity) : "memory");
}
__device__ __forceinline__ void bulk_g2s(uint32_t dst, const void* src, uint32_t bytes,
                                         uint32_t mbar) {
    asm volatile(
        "cp.async.bulk.shared::cta.global.mbarrier::complete_tx::bytes [%0], [%1], %2, [%3];"
        :: "r"(dst), "l"(src), "r"(bytes), "r"(mbar) : "memory");
}
__device__ __forceinline__ void stcs2(float* p, float a, float b) {
    float2 v; v.x = a; v.y = b;
    __stcs(reinterpret_cast<float2*>(p), v);
}

// ---------------------------------------------------------------------------
// Kernel 1 (fused): [prep 256 | agg 4608] blocks in one launch.
// (= R9 champion config, byte-identical behavior)
//
// prep role: conv_w (k,d,o) -> B^T tiles [kker][chunk] of 128 n-rows x 32 k.
// agg role:  gaussian weights + weighted aggregation; one block per (b,q),
//            256 threads, thread owns 4 consecutive d-cols for all 8 kernels;
//            emits single fp16 directly in the swizzled GEMM tile layout.
// ---------------------------------------------------------------------------
__global__ void __launch_bounds__(256, 4) k_agg(
    const float* __restrict__ feats, const float* __restrict__ coords,
    const float* __restrict__ mrho,  const float* __restrict__ mtheta,
    const float* __restrict__ prho,  const float* __restrict__ ptheta,
    const float* __restrict__ convw)
{
    __shared__ __align__(16) char smem_buf[16384];
    const int tid = threadIdx.x;

    if (blockIdx.x < NPREP) {
        // ---------------- prep role ----------------
        const int rb = blockIdx.x;
        const int kc = rb & 31;
        const int kk = rb >> 5;

        float* s = reinterpret_cast<float*>(smem_buf);     // 32 x 128 floats
        const float4* src = reinterpret_cast<const float4*>(
            convw + (size_t)kk * (IND * OUTK) + (size_t)kc * (32 * OUTK));
        float4* sd = reinterpret_cast<float4*>(s);
#pragma unroll
        for (int i = 0; i < 4; i++)
            sd[tid + i * 256] = __ldg(&src[tid + i * 256]);
        __syncthreads();

        const size_t tbase = ((size_t)kk * CHUNKS + kc) * TILE_B;
        const int n   = tid & 127;
        const int gg  = (tid >> 7) * 2;
        const int swz = (n >> 1) & 3;
#pragma unroll
        for (int gi = 0; gi < 2; gi++) {
            const int g = gg + gi;
            union { __half h[8]; uint4 u; } H;
#pragma unroll
            for (int j = 0; j < 8; j++)
                H.h[j] = __float2half_rn(s[(g * 8 + j) * 128 + n]);
            const uint32_t sw = (uint32_t)(n * 64 + 16 * (g ^ swz));
            *reinterpret_cast<uint4*>((char*)g_b_hi + tbase + sw) = H.u;
        }
        return;
    }

    // ---------------- agg role ----------------
    const int bq = blockIdx.x - NPREP;
    ull* w2s = reinterpret_cast<ull*>(smem_buf);   // [NN][NKER], rows 64B

    if (tid < NN) {
        const float rho = coords[((size_t)bq * NN + tid) * 2 + 0];
        const float th  = coords[((size_t)bq * NN + tid) * 2 + 1];
        float w[NKER];
        float s = 0.0f;
        const float TWO_PI = 6.283185307179586f;
#pragma unroll
        for (int k = 0; k < NKER; k++) {
            const float dr = rho - __ldg(&mrho[k]);
            const float pr = __ldg(&prho[k]);
            const float wr = expf(-0.5f * dr * dr / (1e-14f + pr * pr));
            const float fa = fabsf(th - __ldg(&mtheta[k]));
            const float sa = fabsf(TWO_PI - fa);
            const float an = fminf(fa, sa);
            const float pt = __ldg(&ptheta[k]);
            const float wt = expf(-0.5f * an * an / (1e-14f + pt * pt));
            float wv = wr * wt;
            wv = isnan(wv) ? 0.0f : wv;
            w[k] = wv;
            s += wv;
        }
#pragma unroll
        for (int k = 0; k < NKER; k++)
            w2s[tid * NKER + k] = pack2(w[k] / s);
    }
    __syncthreads();

    ull acc[NKER][2];
#pragma unroll
    for (int k = 0; k < NKER; k++) { acc[k][0] = 0ULL; acc[k][1] = 0ULL; }

    const ulonglong2* p = reinterpret_cast<const ulonglong2*>(feats)
                        + (size_t)bq * (NN * IND / 4) + tid;
    const ulonglong2* wrow = reinterpret_cast<const ulonglong2*>(w2s);

#pragma unroll 6
    for (int n = 0; n < NN; n++) {
        const ulonglong2 f = __ldcs(p);     // streaming, evict-first
        p += IND / 4;
#pragma unroll
        for (int kp = 0; kp < 4; kp++) {
            const ulonglong2 wk = wrow[n * 4 + kp];
            fma2(acc[2 * kp + 0][0], f.x, wk.x);
            fma2(acc[2 * kp + 0][1], f.y, wk.x);
            fma2(acc[2 * kp + 1][0], f.x, wk.y);
            fma2(acc[2 * kp + 1][1], f.y, wk.y);
        }
    }

    // store single fp16 into swizzled tile layout (streaming stores)
    const int row   = bq & 127;
    const int mt128 = bq >> 7;
    const int kc    = tid >> 3;
    const int g     = (tid >> 1) & 3;
    const int half_ = tid & 1;
    const uint32_t sw = (uint32_t)(row * 64 + 16 * (g ^ ((row >> 1) & 3)) + 8 * half_);

#pragma unroll
    for (int k = 0; k < NKER; k++) {
        float x0 = __uint_as_float((uint32_t)acc[k][0]);
        float x1 = __uint_as_float((uint32_t)(acc[k][0] >> 32));
        float x2 = __uint_as_float((uint32_t)acc[k][1]);
        float x3 = __uint_as_float((uint32_t)(acc[k][1] >> 32));

        union { __half h[4]; ull u; } H;
        H.h[0] = __float2half_rn(x0);
        H.h[1] = __float2half_rn(x1);
        H.h[2] = __float2half_rn(x2);
        H.h[3] = __float2half_rn(x3);

        const size_t tile = ((size_t)(k * MT + mt128) * CHUNKS + kc) * TILE_B;
        __stcs(reinterpret_cast<ull*>((char*)g_a_hi + tile + sw), H.u);
    }
}

// ---------------------------------------------------------------------------
// Kernel 2: HMMA GEMM, single fp16 pass. (= R9 champion config)
// Block 128x128, 8 warps (warp tile 64x32), 6-stage x 16KB bulk pipeline,
// 96KB smem -> 2 blocks/SM, grid (36,8) = one wave.
// Only change vs R9: out stores are __stcs (write-once data, evict-first).
// ---------------------------------------------------------------------------
#define NST 6
#define STAGE_B 16384   // A 8K | B 8K
#define DSM_B (NST * STAGE_B)

__global__ void __launch_bounds__(256, 2) k_mma(float* __restrict__ out)
{
    extern __shared__ char dsm[];
    __shared__ __align__(8) ull s_mbar[NST];

    const uint32_t sbase = smem_u32(dsm);
    const uint32_t mb    = smem_u32(s_mbar);

    const int tid  = threadIdx.x;
    const int wid  = tid >> 5;
    const int lane = tid & 31;
    const int mt   = blockIdx.x;   // 0..35
    const int kk   = blockIdx.y;   // 0..7

    const int wm = (wid >> 2) * 64;   // warp M offset (0/64)
    const int wn = (wid & 3) * 32;    // warp N offset (0/32/64/96)

    const char* Ab = (const char*)g_a_hi + (size_t)(kk * MT + mt) * CHUNKS * TILE_B;
    const char* Bb = (const char*)g_b_hi + (size_t)kk * CHUNKS * TILE_B;

    auto issue_chunk = [&](int c, int s) {
        const uint32_t sb = sbase + (uint32_t)s * STAGE_B;
        const uint32_t fb = mb + 8u * (uint32_t)s;
        mbar_expect_tx(fb, STAGE_B);
        bulk_g2s(sb + 0,    Ab + (size_t)c * TILE_B, TILE_B, fb);
        bulk_g2s(sb + 8192, Bb + (size_t)c * TILE_B, TILE_B, fb);
    };

    if (tid == 0) {
#pragma unroll
        for (int s = 0; s < NST; s++) mbar_init(mb + 8u * s, 1);
    }
    __syncthreads();
    if (tid == 0) {
#pragma unroll
        for (int s = 0; s < NST - 1; s++) issue_chunk(s, s);
    }

    // ldmatrix per-lane address components
    const int j  = lane >> 3;
    const int rr = lane & 7;
    const int a_row  = wm + ((j & 1) << 3) + rr;   // + 16*i
    const int a_gsel = j >> 1;                     // + 2*ss
    const int swzA   = (a_row >> 1) & 3;
    const int b_n    = wn + ((j >> 1) << 3) + rr;  // + 16*p
    const int b_gsel = j & 1;                      // + 2*ss
    const int swzB   = (b_n >> 1) & 3;

    float acc[4][4][4];
#pragma unroll
    for (int i = 0; i < 4; i++)
#pragma unroll
        for (int t = 0; t < 4; t++)
#pragma unroll
            for (int q = 0; q < 4; q++) acc[i][t][q] = 0.0f;

    int ph[NST] = {0, 0, 0, 0, 0, 0};

    for (int c = 0; c < CHUNKS; c++) {
        const int s = c % NST;
        mbar_wait_acq(mb + 8u * s, ph[s]);
        ph[s] ^= 1;

        const uint32_t sb  = sbase + (uint32_t)s * STAGE_B;
        const uint32_t ahb = sb;
        const uint32_t bhb = sb + 8192;

#pragma unroll
        for (int ss = 0; ss < 2; ss++) {
            uint32_t bh[8];
#pragma unroll
            for (int p = 0; p < 2; p++) {
                const uint32_t boff = (uint32_t)((b_n + 16 * p) * 64
                                    + 16 * ((2 * ss + b_gsel) ^ swzB));
                ldx4(&bh[4 * p], bhb + boff);
            }
#pragma unroll
            for (int i = 0; i < 4; i++) {
                uint32_t ah[4];
                const uint32_t aoff = (uint32_t)((a_row + 16 * i) * 64
                                    + 16 * ((2 * ss + a_gsel) ^ swzA));
                ldx4(ah, ahb + aoff);
#pragma unroll
                for (int t = 0; t < 4; t++)
                    mma16816(acc[i][t], ah, &bh[2 * t]);
            }
        }

        __syncthreads();
        if (c + NST - 1 < CHUNKS && tid == 0)
            issue_chunk(c + NST - 1, (c + NST - 1) % NST);
    }

    // epilogue (streaming stores; out is write-once, never re-read)
#pragma unroll
    for (int i = 0; i < 4; i++) {
        const int r0 = mt * 128 + wm + 16 * i + (lane >> 2);
#pragma unroll
        for (int t = 0; t < 4; t++) {
            const int cN = kk * OUTK + wn + 8 * t + 2 * (lane & 3);
            stcs2(out + (size_t)r0 * OUTD + cN,       acc[i][t][0], acc[i][t][1]);
            stcs2(out + (size_t)(r0 + 8) * OUTD + cN, acc[i][t][2], acc[i][t][3]);
        }
    }
}

// ---------------------------------------------------------------------------
extern "C" void kernel_launch(void* const* d_in, const int* in_sizes, int n_in,
                              void* d_out, int out_size)
{
    const float* feats  = (const float*)d_in[0];
    const float* coords = (const float*)d_in[1];
    const float* mrho   = (const float*)d_in[2];
    const float* mtheta = (const float*)d_in[3];
    const float* prho   = (const float*)d_in[4];
    const float* ptheta = (const float*)d_in[5];
    const float* convw  = (const float*)d_in[6];
    float* out = (float*)d_out;

    cudaFuncSetAttribute(k_mma, cudaFuncAttributeMaxDynamicSharedMemorySize, DSM_B);

    k_agg<<<NPREP + BQ, 256>>>(feats, coords, mrho, mtheta, prho, ptheta, convw);
    dim3 gg(MT, NKER);
    k_mma<<<gg, 256, DSM_B>>>(out);
}